// round 1
// baseline (speedup 1.0000x reference)
#include <cuda_runtime.h>
#include <cuda_bf16.h>
#include <math.h>

// Problem constants
#define B_   8
#define NN   1024
#define D_   512
#define H_   8
#define DH_  64
#define GH_  32
#define BH_  (B_*H_)

// Scratch (device globals: allocation-free rule)
__device__ float g_qkv[3u*B_*H_*NN*DH_];          // Q|K|V each [B,H,N,DH]
__device__ float g_Ab[(size_t)B_*NN*NN];          // blended A  [B,N,N]
__device__ float g_S [(size_t)B_*H_*NN*NN];       // logits/probs [B,H,N,N]
__device__ float g_O [(size_t)B_*NN*D_];          // attn output [B,N,D]

// ---------------------------------------------------------------------------
// Shared 128x128 tile C = A * B^T mainloop (A:[M,K] rm, Bm:[N,K] rm), Kstep=16
// 256 threads, 8x8 micro-tile per thread.
// ---------------------------------------------------------------------------
__device__ __forceinline__ void tileMMA_abt(
    const float* __restrict__ A, const float* __restrict__ Bm,
    int lda, int ldb, int Ktot, int m0, int n0, int t,
    float (*As)[132], float (*Bs)[132], float c[8][8])
{
    const int mload = t >> 1;            // 0..127
    const int kload = (t & 1) << 3;      // 0 or 8
    const int tm    = (t >> 4) << 3;     // 0..120
    const int tn    = (t & 15) << 3;     // 0..120

    for (int k0 = 0; k0 < Ktot; k0 += 16) {
        const float* ap = A  + (size_t)(m0 + mload) * lda + k0 + kload;
        const float* bp = Bm + (size_t)(n0 + mload) * ldb + k0 + kload;
        float4 a0 = *(const float4*)(ap);
        float4 a1 = *(const float4*)(ap + 4);
        float4 b0 = *(const float4*)(bp);
        float4 b1 = *(const float4*)(bp + 4);
        As[kload+0][mload]=a0.x; As[kload+1][mload]=a0.y;
        As[kload+2][mload]=a0.z; As[kload+3][mload]=a0.w;
        As[kload+4][mload]=a1.x; As[kload+5][mload]=a1.y;
        As[kload+6][mload]=a1.z; As[kload+7][mload]=a1.w;
        Bs[kload+0][mload]=b0.x; Bs[kload+1][mload]=b0.y;
        Bs[kload+2][mload]=b0.z; Bs[kload+3][mload]=b0.w;
        Bs[kload+4][mload]=b1.x; Bs[kload+5][mload]=b1.y;
        Bs[kload+6][mload]=b1.z; Bs[kload+7][mload]=b1.w;
        __syncthreads();
        #pragma unroll
        for (int kk = 0; kk < 16; kk++) {
            float4 av0 = *(const float4*)&As[kk][tm];
            float4 av1 = *(const float4*)&As[kk][tm+4];
            float4 bv0 = *(const float4*)&Bs[kk][tn];
            float4 bv1 = *(const float4*)&Bs[kk][tn+4];
            float a[8] = {av0.x,av0.y,av0.z,av0.w,av1.x,av1.y,av1.z,av1.w};
            float b[8] = {bv0.x,bv0.y,bv0.z,bv0.w,bv1.x,bv1.y,bv1.z,bv1.w};
            #pragma unroll
            for (int i = 0; i < 8; i++)
                #pragma unroll
                for (int j = 0; j < 8; j++)
                    c[i][j] = fmaf(a[i], b[j], c[i][j]);
        }
        __syncthreads();
    }
}

// ---------------------------------------------------------------------------
// K1: QKV = x @ W_qkv^T + b, scattered into [3][B,H,N,DH]
// ---------------------------------------------------------------------------
__global__ __launch_bounds__(256) void k1_qkv(
    const float* __restrict__ x, const float* __restrict__ W,
    const float* __restrict__ bqkv)
{
    __shared__ float As[16][132];
    __shared__ float Bs[16][132];
    float c[8][8] = {};
    const int t  = threadIdx.x;
    const int m0 = blockIdx.y * 128;
    const int n0 = blockIdx.x * 128;
    tileMMA_abt(x, W, D_, D_, D_, m0, n0, t, As, Bs, c);

    const int tm = (t >> 4) << 3;
    const int tn = (t & 15) << 3;
    #pragma unroll
    for (int i = 0; i < 8; i++) {
        const int m = m0 + tm + i;
        const int b = m >> 10, iseq = m & 1023;
        #pragma unroll
        for (int j = 0; j < 8; j++) {
            const int n  = n0 + tn + j;
            const int cc = n >> 9, h = (n >> 6) & 7, d = n & 63;
            const float v = c[i][j] + bqkv[n];
            g_qkv[(((size_t)cc*B_ + b)*H_ + h)*NN*DH_ + (size_t)iseq*DH_ + d] = v;
        }
    }
}

// ---------------------------------------------------------------------------
// K2: gate MLP per pair -> A_blended
// ---------------------------------------------------------------------------
__global__ __launch_bounds__(256) void k2_gate(
    const float* __restrict__ Ae, const float* __restrict__ Ap,
    const float* __restrict__ Wg1, const float* __restrict__ bg1,
    const float* __restrict__ Wg2, const float* __restrict__ bg2)
{
    __shared__ float w1a[GH_], w1b[GH_], b1[GH_], w2[GH_];
    __shared__ float b2s;
    const int t = threadIdx.x;
    if (t < GH_) {
        w1a[t] = Wg1[t*2 + 0];
        w1b[t] = Wg1[t*2 + 1];
        b1[t]  = bg1[t];
        w2[t]  = Wg2[t];
    }
    if (t == 0) b2s = bg2[0];
    __syncthreads();

    const size_t idx = (size_t)blockIdx.x * blockDim.x + t;
    const float a = Ae[idx];
    const float p = Ap[idx];
    float z = b2s;
    #pragma unroll
    for (int j = 0; j < GH_; j++) {
        float hpre = fmaf(w1a[j], a, fmaf(w1b[j], p, b1[j]));
        float ge   = 0.5f * hpre * (1.0f + erff(hpre * 0.70710678118654752f));
        z = fmaf(w2[j], ge, z);
    }
    const float g = 1.0f / (1.0f + __expf(-z));
    g_Ab[idx] = fmaf(g, a - p, p);     // g*a + (1-g)*p
}

// ---------------------------------------------------------------------------
// K3a: S = clip(QK^T*scale + softplus(Ab*wb+bb)*bscale, ±50)
// ---------------------------------------------------------------------------
__global__ __launch_bounds__(256) void k3a_logits(
    const float* __restrict__ Wb, const float* __restrict__ bb,
    const float* __restrict__ bsc)
{
    __shared__ float As[16][132];
    __shared__ float Bs[16][132];
    float c[8][8] = {};
    const int t  = threadIdx.x;
    const int bh = blockIdx.z;
    const int b  = bh >> 3, h = bh & 7;
    const int m0 = blockIdx.y * 128;
    const int n0 = blockIdx.x * 128;

    const float* Q  = g_qkv + (size_t)bh * NN * DH_;
    const float* Km = g_qkv + ((size_t)B_*H_ + bh) * NN * DH_;
    tileMMA_abt(Q, Km, DH_, DH_, DH_, m0, n0, t, As, Bs, c);

    const float wbh = Wb[h], bbh = bb[h], sch = bsc[h];
    const float* Abp = g_Ab + (size_t)b * NN * NN;
    float* Sp = g_S + (size_t)bh * NN * NN;

    const int tm = (t >> 4) << 3;
    const int tn = (t & 15) << 3;
    #pragma unroll
    for (int i = 0; i < 8; i++) {
        const int iseq = m0 + tm + i;
        #pragma unroll
        for (int j = 0; j < 8; j++) {
            const int jseq = n0 + tn + j;
            const float ab = Abp[(size_t)iseq*NN + jseq];
            const float zz = fmaf(ab, wbh, bbh);
            const float sp = fmaxf(zz, 0.0f) + log1pf(__expf(-fabsf(zz)));
            float s = fmaf(c[i][j], 0.125f, sp * sch);
            s = fminf(fmaxf(s, -50.0f), 50.0f);
            Sp[(size_t)iseq*NN + jseq] = s;
        }
    }
}

// ---------------------------------------------------------------------------
// K3b: row softmax in place (one block per row of 1024)
// ---------------------------------------------------------------------------
__global__ __launch_bounds__(256) void k3b_softmax()
{
    __shared__ float red[256];
    float* S = g_S + (size_t)blockIdx.x * NN;
    const int t = threadIdx.x;
    float v[4];
    float mx = -1e30f;
    #pragma unroll
    for (int k = 0; k < 4; k++) { v[k] = S[t + k*256]; mx = fmaxf(mx, v[k]); }
    red[t] = mx; __syncthreads();
    for (int s = 128; s > 0; s >>= 1) {
        if (t < s) red[t] = fmaxf(red[t], red[t+s]);
        __syncthreads();
    }
    mx = red[0]; __syncthreads();
    float sum = 0.0f;
    #pragma unroll
    for (int k = 0; k < 4; k++) { v[k] = __expf(v[k] - mx); sum += v[k]; }
    red[t] = sum; __syncthreads();
    for (int s = 128; s > 0; s >>= 1) {
        if (t < s) red[t] += red[t+s];
        __syncthreads();
    }
    const float inv = 1.0f / red[0];
    #pragma unroll
    for (int k = 0; k < 4; k++) S[t + k*256] = v[k] * inv;
}

// ---------------------------------------------------------------------------
// K3c: O = P @ V  (per bh: [1024,1024]@[1024,64]), written as [B,N,D]
// ---------------------------------------------------------------------------
__global__ __launch_bounds__(256) void k3c_av()
{
    __shared__ float Ps[16][132];
    __shared__ float Vs[16][68];
    float c[8][4] = {};
    const int t  = threadIdx.x;
    const int bh = blockIdx.y;
    const int b  = bh >> 3, h = bh & 7;
    const int m0 = blockIdx.x * 128;

    const float* P = g_S + (size_t)bh * NN * NN;
    const float* V = g_qkv + ((size_t)2*B_*H_ + bh) * NN * DH_;

    const int mload = t >> 1;
    const int kload = (t & 1) << 3;
    const int vk = t >> 4;            // 0..15
    const int vn = (t & 15) << 2;     // 0..60
    const int tm = (t >> 4) << 3;
    const int tn = (t & 15) << 2;

    for (int k0 = 0; k0 < NN; k0 += 16) {
        const float* pp = P + (size_t)(m0 + mload) * NN + k0 + kload;
        float4 a0 = *(const float4*)(pp);
        float4 a1 = *(const float4*)(pp + 4);
        Ps[kload+0][mload]=a0.x; Ps[kload+1][mload]=a0.y;
        Ps[kload+2][mload]=a0.z; Ps[kload+3][mload]=a0.w;
        Ps[kload+4][mload]=a1.x; Ps[kload+5][mload]=a1.y;
        Ps[kload+6][mload]=a1.z; Ps[kload+7][mload]=a1.w;
        float4 v4 = *(const float4*)(V + (size_t)(k0 + vk) * DH_ + vn);
        *(float4*)&Vs[vk][vn] = v4;
        __syncthreads();
        #pragma unroll
        for (int kk = 0; kk < 16; kk++) {
            float4 av0 = *(const float4*)&Ps[kk][tm];
            float4 av1 = *(const float4*)&Ps[kk][tm+4];
            float4 bv  = *(const float4*)&Vs[kk][tn];
            float a[8] = {av0.x,av0.y,av0.z,av0.w,av1.x,av1.y,av1.z,av1.w};
            float bb[4] = {bv.x,bv.y,bv.z,bv.w};
            #pragma unroll
            for (int i = 0; i < 8; i++)
                #pragma unroll
                for (int j = 0; j < 4; j++)
                    c[i][j] = fmaf(a[i], bb[j], c[i][j]);
        }
        __syncthreads();
    }

    #pragma unroll
    for (int i = 0; i < 8; i++) {
        const int iseq = m0 + tm + i;
        #pragma unroll
        for (int j = 0; j < 4; j++)
            g_O[((size_t)b*NN + iseq)*D_ + h*DH_ + tn + j] = c[i][j];
    }
}

// ---------------------------------------------------------------------------
// K4: out = O @ W_proj^T + b_proj
// ---------------------------------------------------------------------------
__global__ __launch_bounds__(256) void k4_proj(
    const float* __restrict__ Wp, const float* __restrict__ bp,
    float* __restrict__ out)
{
    __shared__ float As[16][132];
    __shared__ float Bs[16][132];
    float c[8][8] = {};
    const int t  = threadIdx.x;
    const int m0 = blockIdx.y * 128;
    const int n0 = blockIdx.x * 128;
    tileMMA_abt(g_O, Wp, D_, D_, D_, m0, n0, t, As, Bs, c);

    const int tm = (t >> 4) << 3;
    const int tn = (t & 15) << 3;
    #pragma unroll
    for (int i = 0; i < 8; i++) {
        const int m = m0 + tm + i;
        #pragma unroll
        for (int j = 0; j < 8; j++) {
            const int n = n0 + tn + j;
            out[(size_t)m*D_ + n] = c[i][j] + bp[n];
        }
    }
}

// ---------------------------------------------------------------------------
extern "C" void kernel_launch(void* const* d_in, const int* in_sizes, int n_in,
                              void* d_out, int out_size)
{
    const float* x    = (const float*)d_in[0];
    const float* Ae   = (const float*)d_in[1];
    const float* Ap   = (const float*)d_in[2];
    const float* Wqkv = (const float*)d_in[3];
    const float* bqkv = (const float*)d_in[4];
    const float* Wprj = (const float*)d_in[5];
    const float* bprj = (const float*)d_in[6];
    const float* Wg1  = (const float*)d_in[7];
    const float* bg1  = (const float*)d_in[8];
    const float* Wg2  = (const float*)d_in[9];
    const float* bg2  = (const float*)d_in[10];
    const float* Wb   = (const float*)d_in[11];
    const float* bb   = (const float*)d_in[12];
    const float* bsc  = (const float*)d_in[13];
    float* out = (float*)d_out;

    k1_qkv   <<<dim3(12, 64), 256>>>(x, Wqkv, bqkv);
    k2_gate  <<<(B_*NN*NN)/256, 256>>>(Ae, Ap, Wg1, bg1, Wg2, bg2);
    k3a_logits<<<dim3(8, 8, BH_), 256>>>(Wb, bb, bsc);
    k3b_softmax<<<BH_*NN, 256>>>();
    k3c_av   <<<dim3(8, BH_), 256>>>();
    k4_proj  <<<dim3(4, 64), 256>>>(Wprj, bprj, out);
}

// round 2
// speedup vs baseline: 1.7019x; 1.7019x over previous
#include <cuda_runtime.h>
#include <cuda_bf16.h>
#include <math.h>

#define B_   8
#define NN   1024
#define D_   512
#define H_   8
#define DH_  64
#define GH_  32
#define BH_  (B_*H_)

// Scratch (device globals: allocation-free rule)
__device__ float g_qkv[3u*B_*H_*NN*DH_];          // Q|K|V each [B,H,N,DH]
__device__ float g_Ab[(size_t)B_*NN*NN];          // blended A  [B,N,N]
__device__ float g_O [(size_t)B_*NN*D_];          // attn output [B,N,D]

// ---------------------------------------------------------------------------
// 128x128 tile C = A * B^T with register prefetch (A:[M,K] rm, Bm:[N,K] rm)
// 256 threads, 8x8 micro-tile per thread, Kstep=16.
// ---------------------------------------------------------------------------
__device__ __forceinline__ void tileMMA_abt_pf(
    const float* __restrict__ A, const float* __restrict__ Bm,
    int lda, int ldb, int Ktot, int m0, int n0, int t,
    float (*As)[132], float (*Bs)[132], float c[8][8])
{
    const int mload = t >> 1;            // 0..127
    const int kload = (t & 1) << 3;      // 0 or 8
    const int tm    = (t >> 4) << 3;
    const int tn    = (t & 15) << 3;

    const float* ap = A  + (size_t)(m0 + mload) * lda + kload;
    const float* bp = Bm + (size_t)(n0 + mload) * ldb + kload;

    float4 a0 = *(const float4*)(ap);
    float4 a1 = *(const float4*)(ap + 4);
    float4 b0 = *(const float4*)(bp);
    float4 b1 = *(const float4*)(bp + 4);

    for (int k0 = 0; k0 < Ktot; k0 += 16) {
        As[kload+0][mload]=a0.x; As[kload+1][mload]=a0.y;
        As[kload+2][mload]=a0.z; As[kload+3][mload]=a0.w;
        As[kload+4][mload]=a1.x; As[kload+5][mload]=a1.y;
        As[kload+6][mload]=a1.z; As[kload+7][mload]=a1.w;
        Bs[kload+0][mload]=b0.x; Bs[kload+1][mload]=b0.y;
        Bs[kload+2][mload]=b0.z; Bs[kload+3][mload]=b0.w;
        Bs[kload+4][mload]=b1.x; Bs[kload+5][mload]=b1.y;
        Bs[kload+6][mload]=b1.z; Bs[kload+7][mload]=b1.w;
        __syncthreads();
        if (k0 + 16 < Ktot) {               // prefetch next K-slab
            a0 = *(const float4*)(ap + k0 + 16);
            a1 = *(const float4*)(ap + k0 + 20);
            b0 = *(const float4*)(bp + k0 + 16);
            b1 = *(const float4*)(bp + k0 + 20);
        }
        #pragma unroll
        for (int kk = 0; kk < 16; kk++) {
            float4 av0 = *(const float4*)&As[kk][tm];
            float4 av1 = *(const float4*)&As[kk][tm+4];
            float4 bv0 = *(const float4*)&Bs[kk][tn];
            float4 bv1 = *(const float4*)&Bs[kk][tn+4];
            float a[8] = {av0.x,av0.y,av0.z,av0.w,av1.x,av1.y,av1.z,av1.w};
            float b[8] = {bv0.x,bv0.y,bv0.z,bv0.w,bv1.x,bv1.y,bv1.z,bv1.w};
            #pragma unroll
            for (int i = 0; i < 8; i++)
                #pragma unroll
                for (int j = 0; j < 8; j++)
                    c[i][j] = fmaf(a[i], b[j], c[i][j]);
        }
        __syncthreads();
    }
}

// ---------------------------------------------------------------------------
// K1: QKV = x @ W_qkv^T + b, scattered into [3][B,H,N,DH]
// ---------------------------------------------------------------------------
__global__ __launch_bounds__(256) void k1_qkv(
    const float* __restrict__ x, const float* __restrict__ W,
    const float* __restrict__ bqkv)
{
    __shared__ float As[16][132];
    __shared__ float Bs[16][132];
    float c[8][8] = {};
    const int t  = threadIdx.x;
    const int m0 = blockIdx.y * 128;
    const int n0 = blockIdx.x * 128;
    tileMMA_abt_pf(x, W, D_, D_, D_, m0, n0, t, As, Bs, c);

    const int tm = (t >> 4) << 3;
    const int tn = (t & 15) << 3;
    #pragma unroll
    for (int i = 0; i < 8; i++) {
        const int m = m0 + tm + i;
        const int b = m >> 10, iseq = m & 1023;
        #pragma unroll
        for (int j = 0; j < 8; j++) {
            const int n  = n0 + tn + j;
            const int cc = n >> 9, h = (n >> 6) & 7, d = n & 63;
            const float v = c[i][j] + bqkv[n];
            g_qkv[(((size_t)cc*B_ + b)*H_ + h)*NN*DH_ + (size_t)iseq*DH_ + d] = v;
        }
    }
}

// ---------------------------------------------------------------------------
// K2: gate MLP per pair -> A_blended
// ---------------------------------------------------------------------------
__global__ __launch_bounds__(256) void k2_gate(
    const float* __restrict__ Ae, const float* __restrict__ Ap,
    const float* __restrict__ Wg1, const float* __restrict__ bg1,
    const float* __restrict__ Wg2, const float* __restrict__ bg2)
{
    __shared__ float w1a[GH_], w1b[GH_], b1[GH_], w2[GH_];
    __shared__ float b2s;
    const int t = threadIdx.x;
    if (t < GH_) {
        w1a[t] = Wg1[t*2 + 0];
        w1b[t] = Wg1[t*2 + 1];
        b1[t]  = bg1[t];
        w2[t]  = Wg2[t];
    }
    if (t == 0) b2s = bg2[0];
    __syncthreads();

    const size_t idx = (size_t)blockIdx.x * blockDim.x + t;
    const float a = Ae[idx];
    const float p = Ap[idx];
    float z = b2s;
    #pragma unroll
    for (int j = 0; j < GH_; j++) {
        float hpre = fmaf(w1a[j], a, fmaf(w1b[j], p, b1[j]));
        float ge   = 0.5f * hpre * (1.0f + erff(hpre * 0.70710678118654752f));
        z = fmaf(w2[j], ge, z);
    }
    const float g = 1.0f / (1.0f + __expf(-z));
    g_Ab[idx] = fmaf(g, a - p, p);     // g*a + (1-g)*p
}

// ---------------------------------------------------------------------------
// KFLASH: fused  S = clip(QK^T/8 + softplus(Ab*wb+bb)*sc, ±50) ; softmax ; P@V
// One block = 64 query rows of one (b,h). 256 threads.
// smem: Qs[64][68] | U = Kt[64][132] / Ps[128][68] (union) | Vt[128][68]
// ---------------------------------------------------------------------------
#define QS_LD 68
#define KT_LD 132
#define PS_LD 68
#define VT_LD 68
#define SM_QS 0
#define SM_U  (64*QS_LD)
#define SM_VT (SM_U + 8704)            // max(64*132, 128*68) = 8704
#define SM_FLOATS (SM_VT + 128*VT_LD)  // 21760 floats = 87040 bytes

__global__ __launch_bounds__(256) void kflash(
    const float* __restrict__ Wb, const float* __restrict__ bb,
    const float* __restrict__ bsc)
{
    extern __shared__ float sm[];
    float* Qs = sm + SM_QS;
    float* Us = sm + SM_U;
    float* Vt = sm + SM_VT;

    const int t  = threadIdx.x;
    const int mb = blockIdx.x;           // 0..15
    const int bh = blockIdx.y;           // 0..63
    const int b  = bh >> 3, h = bh & 7;
    const int m0 = mb * 64;

    const float* Q  = g_qkv + (size_t)bh * NN * DH_;
    const float* Km = g_qkv + ((size_t)BH_ + bh) * NN * DH_;
    const float* V  = g_qkv + ((size_t)2*BH_ + bh) * NN * DH_;
    const float* Abp = g_Ab + (size_t)b * NN * NN;

    const int rowg = t >> 4;             // 0..15
    const int colg = t & 15;             // 0..15
    const int tm = rowg * 4;
    const int tn = colg * 8;
    const int to = colg * 4;

    // Load Q tile transposed: Qs[k][m] <- Q[m0+m][k]
    {
        const int m  = t >> 2;           // 0..63
        const int kb = (t & 3) * 16;     // 0,16,32,48
        #pragma unroll
        for (int c = 0; c < 4; c++) {
            float4 q = *(const float4*)(Q + (size_t)(m0 + m) * DH_ + kb + c*4);
            Qs[(kb+c*4+0)*QS_LD + m] = q.x;
            Qs[(kb+c*4+1)*QS_LD + m] = q.y;
            Qs[(kb+c*4+2)*QS_LD + m] = q.z;
            Qs[(kb+c*4+3)*QS_LD + m] = q.w;
        }
    }

    float accO[4][4] = {};
    float mrow[4], lrow[4];
    #pragma unroll
    for (int i = 0; i < 4; i++) { mrow[i] = -1e30f; lrow[i] = 0.0f; }

    const float wbh = Wb[h], bbh = bb[h], sch = bsc[h];

    for (int n0 = 0; n0 < NN; n0 += 128) {
        __syncthreads();   // prior-tile PV reads of Us/Vt complete
        // Load K tile transposed (Us as Kt[k][n]) and V tile natural (Vt[n][d])
        {
            const int n   = t >> 1;          // 0..127
            const int k32 = (t & 1) * 32;
            #pragma unroll
            for (int c = 0; c < 8; c++) {
                float4 kv = *(const float4*)(Km + (size_t)(n0+n)*DH_ + k32 + c*4);
                Us[(k32+c*4+0)*KT_LD + n] = kv.x;
                Us[(k32+c*4+1)*KT_LD + n] = kv.y;
                Us[(k32+c*4+2)*KT_LD + n] = kv.z;
                Us[(k32+c*4+3)*KT_LD + n] = kv.w;
                float4 vv = *(const float4*)(V + (size_t)(n0+n)*DH_ + k32 + c*4);
                *(float4*)(Vt + n*VT_LD + k32 + c*4) = vv;
            }
        }
        __syncthreads();

        // S tile: 64x128, K=64
        float s[4][8] = {};
        #pragma unroll 8
        for (int kk = 0; kk < 64; kk++) {
            float4 a  = *(const float4*)(Qs + kk*QS_LD + tm);
            float4 b0 = *(const float4*)(Us + kk*KT_LD + tn);
            float4 b1 = *(const float4*)(Us + kk*KT_LD + tn + 4);
            float av[4] = {a.x, a.y, a.z, a.w};
            float bv[8] = {b0.x,b0.y,b0.z,b0.w,b1.x,b1.y,b1.z,b1.w};
            #pragma unroll
            for (int i = 0; i < 4; i++)
                #pragma unroll
                for (int j = 0; j < 8; j++)
                    s[i][j] = fmaf(av[i], bv[j], s[i][j]);
        }

        // bias + softplus + clip
        #pragma unroll
        for (int i = 0; i < 4; i++) {
            const float* abr = Abp + (size_t)(m0 + tm + i) * NN + n0 + tn;
            float4 ab0 = *(const float4*)(abr);
            float4 ab1 = *(const float4*)(abr + 4);
            float abv[8] = {ab0.x,ab0.y,ab0.z,ab0.w,ab1.x,ab1.y,ab1.z,ab1.w};
            #pragma unroll
            for (int j = 0; j < 8; j++) {
                const float z  = fmaf(abv[j], wbh, bbh);
                const float sp = fmaxf(z, 0.0f) + log1pf(__expf(-fabsf(z)));
                float val = fmaf(s[i][j], 0.125f, sp * sch);
                s[i][j] = fminf(fmaxf(val, -50.0f), 50.0f);
            }
        }

        // online softmax update (row spread over 16 lanes)
        #pragma unroll
        for (int i = 0; i < 4; i++) {
            float mx = s[i][0];
            #pragma unroll
            for (int j = 1; j < 8; j++) mx = fmaxf(mx, s[i][j]);
            #pragma unroll
            for (int off = 8; off > 0; off >>= 1)
                mx = fmaxf(mx, __shfl_xor_sync(0xffffffffu, mx, off, 16));
            const float mnew  = fmaxf(mrow[i], mx);
            const float alpha = __expf(mrow[i] - mnew);
            mrow[i] = mnew;
            float psum = 0.0f;
            #pragma unroll
            for (int j = 0; j < 8; j++) {
                s[i][j] = __expf(s[i][j] - mnew);
                psum += s[i][j];
            }
            #pragma unroll
            for (int off = 8; off > 0; off >>= 1)
                psum += __shfl_xor_sync(0xffffffffu, psum, off, 16);
            lrow[i] = lrow[i] * alpha + psum;
            #pragma unroll
            for (int jj = 0; jj < 4; jj++) accO[i][jj] *= alpha;
        }

        __syncthreads();   // done reading Kt before overwriting as Ps
        // write P transposed: Ps[n][m]
        #pragma unroll
        for (int j = 0; j < 8; j++)
            #pragma unroll
            for (int i = 0; i < 4; i++)
                Us[(tn + j) * PS_LD + tm + i] = s[i][j];
        __syncthreads();

        // O += P @ Vtile   (kk over 128 keys)
        #pragma unroll 4
        for (int kk = 0; kk < 128; kk++) {
            float4 a = *(const float4*)(Us + kk*PS_LD + tm);
            float4 v = *(const float4*)(Vt + kk*VT_LD + to);
            float av[4] = {a.x, a.y, a.z, a.w};
            float vv[4] = {v.x, v.y, v.z, v.w};
            #pragma unroll
            for (int i = 0; i < 4; i++)
                #pragma unroll
                for (int jj = 0; jj < 4; jj++)
                    accO[i][jj] = fmaf(av[i], vv[jj], accO[i][jj]);
        }
    }

    // normalize + write out [B,N,D]
    #pragma unroll
    for (int i = 0; i < 4; i++) {
        const float inv = 1.0f / lrow[i];
        float4 o;
        o.x = accO[i][0]*inv; o.y = accO[i][1]*inv;
        o.z = accO[i][2]*inv; o.w = accO[i][3]*inv;
        *(float4*)(g_O + ((size_t)b*NN + m0 + tm + i) * D_ + h*DH_ + to) = o;
    }
}

// ---------------------------------------------------------------------------
// K4: out = O @ W_proj^T + b_proj
// ---------------------------------------------------------------------------
__global__ __launch_bounds__(256) void k4_proj(
    const float* __restrict__ Wp, const float* __restrict__ bp,
    float* __restrict__ out)
{
    __shared__ float As[16][132];
    __shared__ float Bs[16][132];
    float c[8][8] = {};
    const int t  = threadIdx.x;
    const int m0 = blockIdx.y * 128;
    const int n0 = blockIdx.x * 128;
    tileMMA_abt_pf(g_O, Wp, D_, D_, D_, m0, n0, t, As, Bs, c);

    const int tm = (t >> 4) << 3;
    const int tn = (t & 15) << 3;
    #pragma unroll
    for (int i = 0; i < 8; i++) {
        const int m = m0 + tm + i;
        #pragma unroll
        for (int j = 0; j < 8; j++) {
            const int n = n0 + tn + j;
            out[(size_t)m*D_ + n] = c[i][j] + bp[n];
        }
    }
}

// ---------------------------------------------------------------------------
extern "C" void kernel_launch(void* const* d_in, const int* in_sizes, int n_in,
                              void* d_out, int out_size)
{
    const float* x    = (const float*)d_in[0];
    const float* Ae   = (const float*)d_in[1];
    const float* Ap   = (const float*)d_in[2];
    const float* Wqkv = (const float*)d_in[3];
    const float* bqkv = (const float*)d_in[4];
    const float* Wprj = (const float*)d_in[5];
    const float* bprj = (const float*)d_in[6];
    const float* Wg1  = (const float*)d_in[7];
    const float* bg1  = (const float*)d_in[8];
    const float* Wg2  = (const float*)d_in[9];
    const float* bg2  = (const float*)d_in[10];
    const float* Wb   = (const float*)d_in[11];
    const float* bb   = (const float*)d_in[12];
    const float* bsc  = (const float*)d_in[13];
    float* out = (float*)d_out;

    static bool attr_set = false;
    if (!attr_set) {
        cudaFuncSetAttribute(kflash, cudaFuncAttributeMaxDynamicSharedMemorySize,
                             SM_FLOATS * (int)sizeof(float));
        attr_set = true;
    }

    k1_qkv  <<<dim3(12, 64), 256>>>(x, Wqkv, bqkv);
    k2_gate <<<(B_*NN*NN)/256, 256>>>(Ae, Ap, Wg1, bg1, Wg2, bg2);
    kflash  <<<dim3(16, 64), 256, SM_FLOATS * (int)sizeof(float)>>>(Wb, bb, bsc);
    k4_proj <<<dim3(4, 64), 256>>>(Wprj, bprj, out);
}

// round 4
// speedup vs baseline: 2.0599x; 1.2104x over previous
#include <cuda_runtime.h>
#include <cuda_bf16.h>
#include <mma.h>
#include <math.h>
#include <cstdint>

using namespace nvcuda;

#define B_   8
#define NN   1024
#define D_   512
#define H_   8
#define DH_  64
#define GH_  32
#define BH_  (B_*H_)

// Scratch (device globals: allocation-free rule)
__device__ float g_qkv[3u*B_*H_*NN*DH_];              // Q|K|V each [B,H,N,DH]
__device__ float g_Ab[(size_t)B_*NN*NN];              // blended A  [B,N,N]
__device__ __nv_bfloat16 g_xh[(size_t)B_*NN*D_];      // x hi/lo
__device__ __nv_bfloat16 g_xl[(size_t)B_*NN*D_];
__device__ __nv_bfloat16 g_Wqh[3*D_*D_];              // W_qkv hi/lo
__device__ __nv_bfloat16 g_Wql[3*D_*D_];
__device__ __nv_bfloat16 g_Wph[D_*D_];                // W_proj hi/lo
__device__ __nv_bfloat16 g_Wpl[D_*D_];
__device__ __nv_bfloat16 g_Oh[(size_t)B_*NN*D_];      // attn out hi/lo
__device__ __nv_bfloat16 g_Ol[(size_t)B_*NN*D_];

// ---------------------------------------------------------------------------
// K0: fp32 -> bf16 hi/lo split
// ---------------------------------------------------------------------------
__global__ __launch_bounds__(256) void k0_conv(
    const float* __restrict__ src, __nv_bfloat16* __restrict__ hi,
    __nv_bfloat16* __restrict__ lo, int n)
{
    int idx = blockIdx.x * 256 + threadIdx.x;
    if (idx >= n) return;
    float v = src[idx];
    __nv_bfloat16 h = __float2bfloat16(v);
    hi[idx] = h;
    lo[idx] = __float2bfloat16(v - __bfloat162float(h));
}

// ---------------------------------------------------------------------------
// WMMA 128x128 tile GEMM: C = A @ B^T, A:[M,K] rm (hi/lo), B:[N,K] rm (hi/lo)
// 256 threads (8 warps, 4x2). BK=32. Result left in Cs[128][132] (fp32).
// ---------------------------------------------------------------------------
#define ASLD 40
#define CSLD 132
#define SM_GEMM_BYTES (128*CSLD*4)   // 67584, unions the A/B staging (40960)

__device__ __forceinline__ void wmma_gemm_tile(
    const __nv_bfloat16* __restrict__ Ah, const __nv_bfloat16* __restrict__ Al,
    const __nv_bfloat16* __restrict__ Bh, const __nv_bfloat16* __restrict__ Bl,
    int lda, int ldb, int Ktot, int m0, int n0, char* sm)
{
    __nv_bfloat16* Ash = (__nv_bfloat16*)sm;
    __nv_bfloat16* Asl = Ash + 128*ASLD;
    __nv_bfloat16* Bsh = Asl + 128*ASLD;
    __nv_bfloat16* Bsl = Bsh + 128*ASLD;
    float* Cs = (float*)sm;

    const int t    = threadIdx.x;
    const int wid  = t >> 5;
    const int wm   = (wid >> 1) * 32;   // warp m offset
    const int wn   = (wid & 1) * 64;    // warp n offset
    const int row  = t >> 1;            // 0..127
    const int c16  = (t & 1) * 16;      // 0 or 16

    wmma::fragment<wmma::accumulator, 16, 16, 16, float> acc[2][4];
    #pragma unroll
    for (int i = 0; i < 2; i++)
        #pragma unroll
        for (int j = 0; j < 4; j++)
            wmma::fill_fragment(acc[i][j], 0.0f);

    for (int kk = 0; kk < Ktot; kk += 32) {
        // stage tiles
        {
            const uint4* sa_h = (const uint4*)(Ah + (size_t)(m0+row)*lda + kk + c16);
            const uint4* sa_l = (const uint4*)(Al + (size_t)(m0+row)*lda + kk + c16);
            const uint4* sb_h = (const uint4*)(Bh + (size_t)(n0+row)*ldb + kk + c16);
            const uint4* sb_l = (const uint4*)(Bl + (size_t)(n0+row)*ldb + kk + c16);
            uint4* da_h = (uint4*)(Ash + row*ASLD + c16);
            uint4* da_l = (uint4*)(Asl + row*ASLD + c16);
            uint4* db_h = (uint4*)(Bsh + row*ASLD + c16);
            uint4* db_l = (uint4*)(Bsl + row*ASLD + c16);
            da_h[0] = sa_h[0]; da_h[1] = sa_h[1];
            da_l[0] = sa_l[0]; da_l[1] = sa_l[1];
            db_h[0] = sb_h[0]; db_h[1] = sb_h[1];
            db_l[0] = sb_l[0]; db_l[1] = sb_l[1];
        }
        __syncthreads();

        #pragma unroll
        for (int ks = 0; ks < 2; ks++) {
            const int ko = ks * 16;
            wmma::fragment<wmma::matrix_a, 16,16,16, __nv_bfloat16, wmma::row_major> ah[2], al[2];
            wmma::fragment<wmma::matrix_b, 16,16,16, __nv_bfloat16, wmma::col_major> bh[4], bl[4];
            #pragma unroll
            for (int i = 0; i < 2; i++) {
                wmma::load_matrix_sync(ah[i], Ash + (wm + i*16)*ASLD + ko, ASLD);
                wmma::load_matrix_sync(al[i], Asl + (wm + i*16)*ASLD + ko, ASLD);
            }
            #pragma unroll
            for (int j = 0; j < 4; j++) {
                wmma::load_matrix_sync(bh[j], Bsh + (wn + j*16)*ASLD + ko, ASLD);
                wmma::load_matrix_sync(bl[j], Bsl + (wn + j*16)*ASLD + ko, ASLD);
            }
            #pragma unroll
            for (int i = 0; i < 2; i++)
                #pragma unroll
                for (int j = 0; j < 4; j++) {
                    wmma::mma_sync(acc[i][j], ah[i], bh[j], acc[i][j]);
                    wmma::mma_sync(acc[i][j], ah[i], bl[j], acc[i][j]);
                    wmma::mma_sync(acc[i][j], al[i], bh[j], acc[i][j]);
                }
        }
        __syncthreads();
    }

    // dump accumulators to Cs (unions the staging buffers — all reads done)
    #pragma unroll
    for (int i = 0; i < 2; i++)
        #pragma unroll
        for (int j = 0; j < 4; j++)
            wmma::store_matrix_sync(Cs + (size_t)(wm + i*16)*CSLD + wn + j*16,
                                    acc[i][j], CSLD, wmma::mem_row_major);
    __syncthreads();
}

// ---------------------------------------------------------------------------
// K1: QKV = x @ W_qkv^T + b  -> scatter [3][B,H,N,DH]
// ---------------------------------------------------------------------------
__global__ __launch_bounds__(256) void k1_qkv_mma(const float* __restrict__ bqkv)
{
    extern __shared__ char sm[];
    const int m0 = blockIdx.y * 128;
    const int n0 = blockIdx.x * 128;
    wmma_gemm_tile(g_xh, g_xl, g_Wqh, g_Wql, D_, D_, D_, m0, n0, sm);
    float* Cs = (float*)sm;

    const int t = threadIdx.x;
    for (int idx = t; idx < 128*128; idx += 256) {
        const int mi = idx >> 7, ni = idx & 127;
        const int m = m0 + mi, n = n0 + ni;
        const int b = m >> 10, iseq = m & 1023;
        const int cc = n >> 9, h = (n >> 6) & 7, d = n & 63;
        const float v = Cs[(size_t)mi*CSLD + ni] + bqkv[n];
        g_qkv[(((size_t)cc*B_ + b)*H_ + h)*NN*DH_ + (size_t)iseq*DH_ + d] = v;
    }
}

// ---------------------------------------------------------------------------
// K4: out = O @ W_proj^T + b_proj
// ---------------------------------------------------------------------------
__global__ __launch_bounds__(256) void k4_proj_mma(
    const float* __restrict__ bp, float* __restrict__ out)
{
    extern __shared__ char sm[];
    const int m0 = blockIdx.y * 128;
    const int n0 = blockIdx.x * 128;
    wmma_gemm_tile(g_Oh, g_Ol, g_Wph, g_Wpl, D_, D_, D_, m0, n0, sm);
    float* Cs = (float*)sm;

    const int t = threadIdx.x;
    for (int idx = t; idx < 128*128; idx += 256) {
        const int mi = idx >> 7, ni = idx & 127;
        const int n = n0 + ni;
        out[(size_t)(m0 + mi) * D_ + n] = Cs[(size_t)mi*CSLD + ni] + bp[n];
    }
}

// ---------------------------------------------------------------------------
// K2: gate MLP per pair -> A_blended
// ---------------------------------------------------------------------------
__global__ __launch_bounds__(256) void k2_gate(
    const float* __restrict__ Ae, const float* __restrict__ Ap,
    const float* __restrict__ Wg1, const float* __restrict__ bg1,
    const float* __restrict__ Wg2, const float* __restrict__ bg2)
{
    __shared__ float w1a[GH_], w1b[GH_], b1[GH_], w2[GH_];
    __shared__ float b2s;
    const int t = threadIdx.x;
    if (t < GH_) {
        w1a[t] = Wg1[t*2 + 0];
        w1b[t] = Wg1[t*2 + 1];
        b1[t]  = bg1[t];
        w2[t]  = Wg2[t];
    }
    if (t == 0) b2s = bg2[0];
    __syncthreads();

    const size_t idx = (size_t)blockIdx.x * blockDim.x + t;
    const float a = Ae[idx];
    const float p = Ap[idx];
    float z = b2s;
    #pragma unroll
    for (int j = 0; j < GH_; j++) {
        float hpre = fmaf(w1a[j], a, fmaf(w1b[j], p, b1[j]));
        float ge   = 0.5f * hpre * (1.0f + erff(hpre * 0.70710678118654752f));
        z = fmaf(w2[j], ge, z);
    }
    const float g = 1.0f / (1.0f + __expf(-z));
    g_Ab[idx] = fmaf(g, a - p, p);     // g*a + (1-g)*p
}

// ---------------------------------------------------------------------------
// KFLASH: fused  S = clip(QK^T/8 + softplus(Ab*wb+bb)*sc, ±50) ; softmax ; P@V
// Writes O as bf16 hi/lo for k4.
// ---------------------------------------------------------------------------
#define QS_LD 68
#define KT_LD 132
#define PS_LD 68
#define VT_LD 68
#define SM_QS 0
#define SM_U  (64*QS_LD)
#define SM_VT (SM_U + 8704)
#define SM_FLOATS (SM_VT + 128*VT_LD)

__global__ __launch_bounds__(256) void kflash(
    const float* __restrict__ Wb, const float* __restrict__ bb,
    const float* __restrict__ bsc)
{
    extern __shared__ float smf[];
    float* Qs = smf + SM_QS;
    float* Us = smf + SM_U;
    float* Vt = smf + SM_VT;

    const int t  = threadIdx.x;
    const int mb = blockIdx.x;
    const int bh = blockIdx.y;
    const int b  = bh >> 3, h = bh & 7;
    const int m0 = mb * 64;

    const float* Q  = g_qkv + (size_t)bh * NN * DH_;
    const float* Km = g_qkv + ((size_t)BH_ + bh) * NN * DH_;
    const float* V  = g_qkv + ((size_t)2*BH_ + bh) * NN * DH_;
    const float* Abp = g_Ab + (size_t)b * NN * NN;

    const int rowg = t >> 4;
    const int colg = t & 15;
    const int tm = rowg * 4;
    const int tn = colg * 8;
    const int to = colg * 4;

    {
        const int m  = t >> 2;
        const int kb = (t & 3) * 16;
        #pragma unroll
        for (int c = 0; c < 4; c++) {
            float4 q = *(const float4*)(Q + (size_t)(m0 + m) * DH_ + kb + c*4);
            Qs[(kb+c*4+0)*QS_LD + m] = q.x;
            Qs[(kb+c*4+1)*QS_LD + m] = q.y;
            Qs[(kb+c*4+2)*QS_LD + m] = q.z;
            Qs[(kb+c*4+3)*QS_LD + m] = q.w;
        }
    }

    float accO[4][4] = {};
    float mrow[4], lrow[4];
    #pragma unroll
    for (int i = 0; i < 4; i++) { mrow[i] = -1e30f; lrow[i] = 0.0f; }

    const float wbh = Wb[h], bbh = bb[h], sch = bsc[h];

    for (int n0 = 0; n0 < NN; n0 += 128) {
        __syncthreads();
        {
            const int n   = t >> 1;
            const int k32 = (t & 1) * 32;
            #pragma unroll
            for (int c = 0; c < 8; c++) {
                float4 kv = *(const float4*)(Km + (size_t)(n0+n)*DH_ + k32 + c*4);
                Us[(k32+c*4+0)*KT_LD + n] = kv.x;
                Us[(k32+c*4+1)*KT_LD + n] = kv.y;
                Us[(k32+c*4+2)*KT_LD + n] = kv.z;
                Us[(k32+c*4+3)*KT_LD + n] = kv.w;
                float4 vv = *(const float4*)(V + (size_t)(n0+n)*DH_ + k32 + c*4);
                *(float4*)(Vt + n*VT_LD + k32 + c*4) = vv;
            }
        }
        __syncthreads();

        float s[4][8] = {};
        #pragma unroll 8
        for (int kk = 0; kk < 64; kk++) {
            float4 a  = *(const float4*)(Qs + kk*QS_LD + tm);
            float4 b0 = *(const float4*)(Us + kk*KT_LD + tn);
            float4 b1 = *(const float4*)(Us + kk*KT_LD + tn + 4);
            float av[4] = {a.x, a.y, a.z, a.w};
            float bv[8] = {b0.x,b0.y,b0.z,b0.w,b1.x,b1.y,b1.z,b1.w};
            #pragma unroll
            for (int i = 0; i < 4; i++)
                #pragma unroll
                for (int j = 0; j < 8; j++)
                    s[i][j] = fmaf(av[i], bv[j], s[i][j]);
        }

        #pragma unroll
        for (int i = 0; i < 4; i++) {
            const float* abr = Abp + (size_t)(m0 + tm + i) * NN + n0 + tn;
            float4 ab0 = *(const float4*)(abr);
            float4 ab1 = *(const float4*)(abr + 4);
            float abv[8] = {ab0.x,ab0.y,ab0.z,ab0.w,ab1.x,ab1.y,ab1.z,ab1.w};
            #pragma unroll
            for (int j = 0; j < 8; j++) {
                const float z  = fmaf(abv[j], wbh, bbh);
                const float sp = fmaxf(z, 0.0f) + log1pf(__expf(-fabsf(z)));
                float val = fmaf(s[i][j], 0.125f, sp * sch);
                s[i][j] = fminf(fmaxf(val, -50.0f), 50.0f);
            }
        }

        #pragma unroll
        for (int i = 0; i < 4; i++) {
            float mx = s[i][0];
            #pragma unroll
            for (int j = 1; j < 8; j++) mx = fmaxf(mx, s[i][j]);
            #pragma unroll
            for (int off = 8; off > 0; off >>= 1)
                mx = fmaxf(mx, __shfl_xor_sync(0xffffffffu, mx, off, 16));
            const float mnew  = fmaxf(mrow[i], mx);
            const float alpha = __expf(mrow[i] - mnew);
            mrow[i] = mnew;
            float psum = 0.0f;
            #pragma unroll
            for (int j = 0; j < 8; j++) {
                s[i][j] = __expf(s[i][j] - mnew);
                psum += s[i][j];
            }
            #pragma unroll
            for (int off = 8; off > 0; off >>= 1)
                psum += __shfl_xor_sync(0xffffffffu, psum, off, 16);
            lrow[i] = lrow[i] * alpha + psum;
            #pragma unroll
            for (int jj = 0; jj < 4; jj++) accO[i][jj] *= alpha;
        }

        __syncthreads();
        #pragma unroll
        for (int j = 0; j < 8; j++)
            #pragma unroll
            for (int i = 0; i < 4; i++)
                Us[(tn + j) * PS_LD + tm + i] = s[i][j];
        __syncthreads();

        #pragma unroll 4
        for (int kk = 0; kk < 128; kk++) {
            float4 a = *(const float4*)(Us + kk*PS_LD + tm);
            float4 v = *(const float4*)(Vt + kk*VT_LD + to);
            float av[4] = {a.x, a.y, a.z, a.w};
            float vv[4] = {v.x, v.y, v.z, v.w};
            #pragma unroll
            for (int i = 0; i < 4; i++)
                #pragma unroll
                for (int jj = 0; jj < 4; jj++)
                    accO[i][jj] = fmaf(av[i], vv[jj], accO[i][jj]);
        }
    }

    #pragma unroll
    for (int i = 0; i < 4; i++) {
        const float inv = 1.0f / lrow[i];
        const size_t off = ((size_t)b*NN + m0 + tm + i) * D_ + h*DH_ + to;
        #pragma unroll
        for (int jj = 0; jj < 4; jj++) {
            const float v = accO[i][jj] * inv;
            __nv_bfloat16 hv = __float2bfloat16(v);
            g_Oh[off + jj] = hv;
            g_Ol[off + jj] = __float2bfloat16(v - __bfloat162float(hv));
        }
    }
}

// ---------------------------------------------------------------------------
extern "C" void kernel_launch(void* const* d_in, const int* in_sizes, int n_in,
                              void* d_out, int out_size)
{
    const float* x    = (const float*)d_in[0];
    const float* Ae   = (const float*)d_in[1];
    const float* Ap   = (const float*)d_in[2];
    const float* Wqkv = (const float*)d_in[3];
    const float* bqkv = (const float*)d_in[4];
    const float* Wprj = (const float*)d_in[5];
    const float* bprj = (const float*)d_in[6];
    const float* Wg1  = (const float*)d_in[7];
    const float* bg1  = (const float*)d_in[8];
    const float* Wg2  = (const float*)d_in[9];
    const float* bg2  = (const float*)d_in[10];
    const float* Wb   = (const float*)d_in[11];
    const float* bb   = (const float*)d_in[12];
    const float* bsc  = (const float*)d_in[13];
    float* out = (float*)d_out;

    static bool attr_set = false;
    if (!attr_set) {
        cudaFuncSetAttribute(kflash, cudaFuncAttributeMaxDynamicSharedMemorySize,
                             SM_FLOATS * (int)sizeof(float));
        cudaFuncSetAttribute(k1_qkv_mma, cudaFuncAttributeMaxDynamicSharedMemorySize,
                             SM_GEMM_BYTES);
        cudaFuncSetAttribute(k4_proj_mma, cudaFuncAttributeMaxDynamicSharedMemorySize,
                             SM_GEMM_BYTES);
        attr_set = true;
    }

    // resolve device-global addresses (host-side; cached after first call)
    static __nv_bfloat16 *xh=nullptr,*xl,*wqh,*wql,*wph,*wpl;
    if (!xh) {
        cudaGetSymbolAddress((void**)&xh,  g_xh);
        cudaGetSymbolAddress((void**)&xl,  g_xl);
        cudaGetSymbolAddress((void**)&wqh, g_Wqh);
        cudaGetSymbolAddress((void**)&wql, g_Wql);
        cudaGetSymbolAddress((void**)&wph, g_Wph);
        cudaGetSymbolAddress((void**)&wpl, g_Wpl);
    }

    const int nx = B_*NN*D_;      // 4,194,304
    const int nq = 3*D_*D_;       // 786,432
    const int np = D_*D_;         // 262,144
    k0_conv<<<(nx+255)/256, 256>>>(x,    xh,  xl,  nx);
    k0_conv<<<(nq+255)/256, 256>>>(Wqkv, wqh, wql, nq);
    k0_conv<<<(np+255)/256, 256>>>(Wprj, wph, wpl, np);

    k1_qkv_mma <<<dim3(12, 64), 256, SM_GEMM_BYTES>>>(bqkv);
    k2_gate    <<<(B_*NN*NN)/256, 256>>>(Ae, Ap, Wg1, bg1, Wg2, bg2);
    kflash     <<<dim3(16, 64), 256, SM_FLOATS * (int)sizeof(float)>>>(Wb, bb, bsc);
    k4_proj_mma<<<dim3(4, 64), 256, SM_GEMM_BYTES>>>(bprj, out);
}

// round 6
// speedup vs baseline: 3.7406x; 1.8159x over previous
#include <cuda_runtime.h>
#include <cuda_bf16.h>
#include <mma.h>
#include <math.h>
#include <cstdint>

using namespace nvcuda;
typedef __nv_bfloat16 bf16;

#define B_   8
#define NN   1024
#define D_   512
#define H_   8
#define DH_  64
#define GH_  32
#define BH_  (B_*H_)

// Scratch (device globals)
__device__ float g_Ab[(size_t)B_*NN*NN];              // blended A [B,N,N]
__device__ bf16 g_qkvh[3u*BH_*NN*DH_];                // Q|K|V hi
__device__ bf16 g_qkvl[3u*BH_*NN*DH_];                // Q|K|V lo
__device__ bf16 g_xh[(size_t)B_*NN*D_];
__device__ bf16 g_xl[(size_t)B_*NN*D_];
__device__ bf16 g_Wqh[3*D_*D_];
__device__ bf16 g_Wql[3*D_*D_];
__device__ bf16 g_Wph[D_*D_];
__device__ bf16 g_Wpl[D_*D_];
__device__ bf16 g_Oh[(size_t)B_*NN*D_];
__device__ bf16 g_Ol[(size_t)B_*NN*D_];

// ---------------------------------------------------------------------------
__device__ __forceinline__ void cp16(void* smem_ptr, const void* gptr) {
    uint32_t s = (uint32_t)__cvta_generic_to_shared(smem_ptr);
    asm volatile("cp.async.cg.shared.global [%0], [%1], 16;" :: "r"(s), "l"(gptr));
}
#define CP_COMMIT() asm volatile("cp.async.commit_group;")
#define CP_WAIT(n)  asm volatile("cp.async.wait_group %0;" :: "n"(n))

__device__ __forceinline__ float tanh_apx(float x) {
    float y;
    asm("tanh.approx.f32 %0, %1;" : "=f"(y) : "f"(x));
    return y;
}

// ---------------------------------------------------------------------------
// K0: fp32 -> bf16 hi/lo split
// ---------------------------------------------------------------------------
__global__ __launch_bounds__(256) void k0_conv(
    const float* __restrict__ src, bf16* __restrict__ hi,
    bf16* __restrict__ lo, int n)
{
    int idx = blockIdx.x * 256 + threadIdx.x;
    if (idx >= n) return;
    float v = src[idx];
    bf16 h = __float2bfloat16(v);
    hi[idx] = h;
    lo[idx] = __float2bfloat16(v - __bfloat162float(h));
}

// ---------------------------------------------------------------------------
// WMMA 128x128 GEMM tile with cp.async double buffering.
// C = A @ B^T ; A,B bf16 hi/lo [rows][K] row-major. Result in Cs[128][136].
// 256 threads (8 warps 4x2). Staging: 2 stages x 4 arrays x [128][40] bf16.
// Each K-slab row = 32 bf16 = 64 B = 4 chunks -> 2048 chunks = 8 rounds.
// ---------------------------------------------------------------------------
#define ASLD 40
#define CSLD 136
#define STAGE_B 40960
#define SM_GEMM_BYTES (2*STAGE_B)   // 81920 >= 128*136*4=69632 for Cs union

__device__ __forceinline__ void wmma_gemm_cp(
    const bf16* __restrict__ Ah, const bf16* __restrict__ Al,
    const bf16* __restrict__ Bh, const bf16* __restrict__ Bl,
    int lda, int ldb, int Ktot, int m0, int n0, char* sm)
{
    const int t   = threadIdx.x;
    const int wid = t >> 5;
    const int wm  = (wid >> 1) * 32;
    const int wn  = (wid & 1) * 64;

    wmma::fragment<wmma::accumulator, 16,16,16, float> acc[2][4];
    #pragma unroll
    for (int i = 0; i < 2; i++)
        #pragma unroll
        for (int j = 0; j < 4; j++) wmma::fill_fragment(acc[i][j], 0.0f);

    const int niter = Ktot / 32;
    auto issue = [&](int ch, int s) {
        const int kk = ch * 32;
        #pragma unroll
        for (int k = 0; k < 8; k++) {
            int c = k * 256 + t;                 // 0..2047
            int arr = c >> 9;                    // 0..3
            int row = (c >> 2) & 127;
            int hh  = c & 3;                     // 4 x 16B per row
            const bf16* base = (arr == 0) ? Ah : (arr == 1) ? Al : (arr == 2) ? Bh : Bl;
            int roff = ((arr < 2) ? m0 : n0) + row;
            int ld   = (arr < 2) ? lda : ldb;
            cp16(sm + s*STAGE_B + arr*10240 + row*80 + hh*16,
                 base + (size_t)roff*ld + kk + hh*8);
        }
        CP_COMMIT();
    };

    issue(0, 0);
    for (int ch = 0; ch < niter; ch++) {
        const int s = ch & 1;
        if (ch + 1 < niter) { issue(ch + 1, s ^ 1); CP_WAIT(1); }
        else                { CP_WAIT(0); }
        __syncthreads();

        bf16* Ash = (bf16*)(sm + s*STAGE_B);
        bf16* Asl = Ash + 128*ASLD;
        bf16* Bsh = Asl + 128*ASLD;
        bf16* Bsl = Bsh + 128*ASLD;

        #pragma unroll
        for (int ks = 0; ks < 2; ks++) {
            const int ko = ks * 16;
            wmma::fragment<wmma::matrix_a, 16,16,16, bf16, wmma::row_major> ah[2], al[2];
            #pragma unroll
            for (int i = 0; i < 2; i++) {
                wmma::load_matrix_sync(ah[i], Ash + (wm + i*16)*ASLD + ko, ASLD);
                wmma::load_matrix_sync(al[i], Asl + (wm + i*16)*ASLD + ko, ASLD);
            }
            #pragma unroll
            for (int j = 0; j < 4; j++) {
                wmma::fragment<wmma::matrix_b, 16,16,16, bf16, wmma::col_major> bh, bl;
                wmma::load_matrix_sync(bh, Bsh + (wn + j*16)*ASLD + ko, ASLD);
                wmma::load_matrix_sync(bl, Bsl + (wn + j*16)*ASLD + ko, ASLD);
                #pragma unroll
                for (int i = 0; i < 2; i++) {
                    wmma::mma_sync(acc[i][j], ah[i], bh, acc[i][j]);
                    wmma::mma_sync(acc[i][j], ah[i], bl, acc[i][j]);
                    wmma::mma_sync(acc[i][j], al[i], bh, acc[i][j]);
                }
            }
        }
        __syncthreads();
    }

    float* Cs = (float*)sm;
    #pragma unroll
    for (int i = 0; i < 2; i++)
        #pragma unroll
        for (int j = 0; j < 4; j++)
            wmma::store_matrix_sync(Cs + (size_t)(wm + i*16)*CSLD + wn + j*16,
                                    acc[i][j], CSLD, wmma::mem_row_major);
    __syncthreads();
}

// ---------------------------------------------------------------------------
// K1: QKV = x @ W_qkv^T + b  -> scatter [3][B,H,N,DH] as bf16 hi/lo
// ---------------------------------------------------------------------------
__global__ __launch_bounds__(256) void k1_qkv_mma(const float* __restrict__ bqkv)
{
    extern __shared__ char sm[];
    const int m0 = blockIdx.y * 128;
    const int n0 = blockIdx.x * 128;
    wmma_gemm_cp(g_xh, g_xl, g_Wqh, g_Wql, D_, D_, D_, m0, n0, sm);
    float* Cs = (float*)sm;

    const int t = threadIdx.x;
    for (int idx = t; idx < 128*128; idx += 256) {
        const int mi = idx >> 7, ni = idx & 127;
        const int m = m0 + mi, n = n0 + ni;
        const int b = m >> 10, iseq = m & 1023;
        const int cc = n >> 9, h = (n >> 6) & 7, d = n & 63;
        const float v = Cs[(size_t)mi*CSLD + ni] + bqkv[n];
        const size_t o = (((size_t)cc*B_ + b)*H_ + h)*NN*DH_ + (size_t)iseq*DH_ + d;
        bf16 hv = __float2bfloat16(v);
        g_qkvh[o] = hv;
        g_qkvl[o] = __float2bfloat16(v - __bfloat162float(hv));
    }
}

// ---------------------------------------------------------------------------
// K4: out = O @ W_proj^T + b_proj
// ---------------------------------------------------------------------------
__global__ __launch_bounds__(256) void k4_proj_mma(
    const float* __restrict__ bp, float* __restrict__ out)
{
    extern __shared__ char sm[];
    const int m0 = blockIdx.y * 128;
    const int n0 = blockIdx.x * 128;
    wmma_gemm_cp(g_Oh, g_Ol, g_Wph, g_Wpl, D_, D_, D_, m0, n0, sm);
    float* Cs = (float*)sm;

    const int t = threadIdx.x;
    for (int idx = t; idx < 128*128; idx += 256) {
        const int mi = idx >> 7, ni = idx & 127;
        const int n = n0 + ni;
        out[(size_t)(m0 + mi) * D_ + n] = Cs[(size_t)mi*CSLD + ni] + bp[n];
    }
}

// ---------------------------------------------------------------------------
// K2: gate MLP per pair -> A_blended   (tanh-form GELU, tanh.approx)
// ---------------------------------------------------------------------------
__global__ __launch_bounds__(256) void k2_gate(
    const float* __restrict__ Ae, const float* __restrict__ Ap,
    const float* __restrict__ Wg1, const float* __restrict__ bg1,
    const float* __restrict__ Wg2, const float* __restrict__ bg2)
{
    __shared__ float w1a[GH_], w1b[GH_], b1[GH_], w2[GH_];
    __shared__ float b2s;
    const int t = threadIdx.x;
    if (t < GH_) {
        w1a[t] = Wg1[t*2 + 0];
        w1b[t] = Wg1[t*2 + 1];
        b1[t]  = bg1[t];
        w2[t]  = Wg2[t];
    }
    if (t == 0) b2s = bg2[0];
    __syncthreads();

    const size_t idx = (size_t)blockIdx.x * blockDim.x + t;
    const float a = Ae[idx];
    const float p = Ap[idx];
    float z = b2s;
    #pragma unroll
    for (int j = 0; j < GH_; j++) {
        float hh = fmaf(w1a[j], a, fmaf(w1b[j], p, b1[j]));
        float inner = 0.7978845608028654f * hh * fmaf(0.044715f, hh*hh, 1.0f);
        float ge = 0.5f * hh * (1.0f + tanh_apx(inner));
        z = fmaf(w2[j], ge, z);
    }
    const float g = 1.0f / (1.0f + __expf(-z));
    g_Ab[idx] = fmaf(g, a - p, p);
}

// ---------------------------------------------------------------------------
// KFLASH (WMMA): per block 64 q-rows of one (b,h).
// Clip at ±50 => exp never overflows => no max subtraction, no rescale:
// O accumulates in persistent wmma accumulators; divide by rowsum at end.
// ---------------------------------------------------------------------------
#define KF_QH 0              // Qh [64][80] bf16 = 10240
#define KF_QL 10240
#define KF_VH 20480          // Vh [128][80] bf16 = 20480
#define KF_VL 40960
#define KF_U  61440          // union: Kh+Kl (2x20480) / S f32 [64][136] / Ph+Pl (2x17408)
#define KF_RS 102400         // rowsum [64] f32
#define KF_BYTES 102656

__global__ __launch_bounds__(256) void kflash_mma(
    const float* __restrict__ Wb, const float* __restrict__ bb,
    const float* __restrict__ bsc)
{
    extern __shared__ char sm[];
    const int t   = threadIdx.x;
    const int wid = t >> 5;
    const int mb  = blockIdx.x;          // 0..15
    const int bh  = blockIdx.y;          // 0..63
    const int b   = bh >> 3, h = bh & 7;
    const int m0  = mb * 64;

    const size_t Qoff = (size_t)bh * NN * DH_;
    const size_t Koff = ((size_t)BH_ + bh) * NN * DH_;
    const size_t Voff = ((size_t)2*BH_ + bh) * NN * DH_;
    const float* Abp  = g_Ab + (size_t)b * NN * NN;

    // --- load Q tile (hi/lo) via cp.async: 2 arrays x 64 rows x 8 chunks ---
    #pragma unroll
    for (int k = 0; k < 4; k++) {
        int c = k * 256 + t;
        int arr = c >> 9, row = (c >> 3) & 63, cc = c & 7;
        const bf16* src = (arr ? g_qkvl : g_qkvh) + Qoff + (size_t)(m0 + row)*DH_ + cc*8;
        cp16(sm + (arr ? KF_QL : KF_QH) + row*160 + cc*16, src);
    }
    CP_COMMIT();

    // warp tiles
    const int wmS = (wid >> 1) * 16, wnS = (wid & 1) * 64;   // S: 64x128
    const int wmO = (wid >> 1) * 16, wnO = (wid & 1) * 32;   // O: 64x64

    wmma::fragment<wmma::accumulator, 16,16,16, float> accO[2];
    #pragma unroll
    for (int j = 0; j < 2; j++) wmma::fill_fragment(accO[j], 0.0f);

    const int r_row = t >> 2;            // 0..63
    const int c0    = (t & 3) * 32;      // 0..96
    float rs = 0.0f;

    const float wbh = Wb[h], bbh = bb[h], sch = bsc[h];

    for (int tile = 0; tile < 8; tile++) {
        const int n0 = tile * 128;
        __syncthreads();   // prior-tile readers of U / V done

        // --- load K,V tiles (hi/lo): 4 arrays x 128 rows x 8 chunks ---
        #pragma unroll
        for (int k = 0; k < 16; k++) {
            int c = k * 256 + t;
            int arr = c >> 10, row = (c >> 3) & 127, cc = c & 7;
            const bf16* gb = (arr == 0) ? g_qkvh + Koff : (arr == 1) ? g_qkvl + Koff
                           : (arr == 2) ? g_qkvh + Voff : g_qkvl + Voff;
            char* db = (arr == 0) ? sm + KF_U : (arr == 1) ? sm + KF_U + 20480
                     : (arr == 2) ? sm + KF_VH : sm + KF_VL;
            cp16(db + row*160 + cc*16, gb + (size_t)(n0 + row)*DH_ + cc*8);
        }
        CP_COMMIT();
        CP_WAIT(0);
        __syncthreads();

        // --- QK^T: S[64][128], K=64, 3 streams ---
        bf16* Qh = (bf16*)(sm + KF_QH);
        bf16* Ql = (bf16*)(sm + KF_QL);
        bf16* Kh = (bf16*)(sm + KF_U);
        bf16* Kl = (bf16*)(sm + KF_U + 20480);
        wmma::fragment<wmma::accumulator, 16,16,16, float> accS[4];
        #pragma unroll
        for (int j = 0; j < 4; j++) wmma::fill_fragment(accS[j], 0.0f);
        #pragma unroll
        for (int ks = 0; ks < 4; ks++) {
            const int ko = ks * 16;
            wmma::fragment<wmma::matrix_a, 16,16,16, bf16, wmma::row_major> ah, al;
            wmma::load_matrix_sync(ah, Qh + wmS*80 + ko, 80);
            wmma::load_matrix_sync(al, Ql + wmS*80 + ko, 80);
            #pragma unroll
            for (int j = 0; j < 4; j++) {
                wmma::fragment<wmma::matrix_b, 16,16,16, bf16, wmma::col_major> bh_f, bl_f;
                wmma::load_matrix_sync(bh_f, Kh + (wnS + j*16)*80 + ko, 80);
                wmma::load_matrix_sync(bl_f, Kl + (wnS + j*16)*80 + ko, 80);
                wmma::mma_sync(accS[j], ah, bh_f, accS[j]);
                wmma::mma_sync(accS[j], ah, bl_f, accS[j]);
                wmma::mma_sync(accS[j], al, bh_f, accS[j]);
            }
        }
        __syncthreads();   // all K reads done; U becomes S
        float* Ssm = (float*)(sm + KF_U);
        #pragma unroll
        for (int j = 0; j < 4; j++)
            wmma::store_matrix_sync(Ssm + wmS*136 + wnS + j*16, accS[j], 136,
                                    wmma::mem_row_major);
        __syncthreads();

        // --- bias + softplus + clip + exp ; rowsum ; P = exp(S) hi/lo ---
        float pv[32];
        {
            const float* srow = Ssm + r_row*136 + c0;
            const float* abr  = Abp + (size_t)(m0 + r_row)*NN + n0 + c0;
            #pragma unroll
            for (int q = 0; q < 8; q++) {
                float4 s4 = ((const float4*)srow)[q];
                float4 a4 = ((const float4*)abr)[q];
                float sv[4] = {s4.x, s4.y, s4.z, s4.w};
                float av[4] = {a4.x, a4.y, a4.z, a4.w};
                #pragma unroll
                for (int kq = 0; kq < 4; kq++) {
                    float z  = fmaf(av[kq], wbh, bbh);
                    float sp = fmaxf(z, 0.0f) + log1pf(__expf(-fabsf(z)));
                    float val = fmaf(sv[kq], 0.125f, sp * sch);
                    val = fminf(fmaxf(val, -50.0f), 50.0f);
                    float pq = __expf(val);
                    rs += pq;
                    pv[q*4 + kq] = pq;
                }
            }
        }
        __syncthreads();   // all S reads done; U becomes P
        {
            bf16* Php = (bf16*)(sm + KF_U) + r_row*136 + c0;
            bf16* Plp = (bf16*)(sm + KF_U + 17408) + r_row*136 + c0;
            #pragma unroll
            for (int q = 0; q < 32; q++) {
                bf16 hv = __float2bfloat16(pv[q]);
                Php[q] = hv;
                Plp[q] = __float2bfloat16(pv[q] - __bfloat162float(hv));
            }
        }
        __syncthreads();

        // --- O += P @ V (K=128), 3 streams ---
        bf16* Ph = (bf16*)(sm + KF_U);
        bf16* Pl = (bf16*)(sm + KF_U + 17408);
        bf16* Vh = (bf16*)(sm + KF_VH);
        bf16* Vl = (bf16*)(sm + KF_VL);
        #pragma unroll
        for (int ks = 0; ks < 8; ks++) {
            const int ko = ks * 16;
            wmma::fragment<wmma::matrix_a, 16,16,16, bf16, wmma::row_major> pah, pal;
            wmma::load_matrix_sync(pah, Ph + wmO*136 + ko, 136);
            wmma::load_matrix_sync(pal, Pl + wmO*136 + ko, 136);
            #pragma unroll
            for (int j = 0; j < 2; j++) {
                wmma::fragment<wmma::matrix_b, 16,16,16, bf16, wmma::row_major> vbh, vbl;
                wmma::load_matrix_sync(vbh, Vh + ko*80 + wnO + j*16, 80);
                wmma::load_matrix_sync(vbl, Vl + ko*80 + wnO + j*16, 80);
                wmma::mma_sync(accO[j], pah, vbh, accO[j]);
                wmma::mma_sync(accO[j], pah, vbl, accO[j]);
                wmma::mma_sync(accO[j], pal, vbh, accO[j]);
            }
        }
    }

    // --- finalize: O/rowsum -> g_Oh/g_Ol ---
    __syncthreads();
    float* Osm = (float*)(sm + KF_U);
    #pragma unroll
    for (int j = 0; j < 2; j++)
        wmma::store_matrix_sync(Osm + wmO*72 + wnO + j*16, accO[j], 72,
                                wmma::mem_row_major);
    // rowsum reduce (4 threads per row)
    rs += __shfl_xor_sync(0xffffffffu, rs, 1, 4);
    rs += __shfl_xor_sync(0xffffffffu, rs, 2, 4);
    float* rowsum = (float*)(sm + KF_RS);
    if ((t & 3) == 0) rowsum[r_row] = rs;
    __syncthreads();

    {
        const int r  = t >> 2;
        const int cc = (t & 3) * 16;
        const float inv = 1.0f / rowsum[r];
        const size_t off = ((size_t)b*NN + m0 + r) * D_ + h*DH_ + cc;
        #pragma unroll
        for (int q = 0; q < 16; q++) {
            float o = Osm[r*72 + cc + q] * inv;
            bf16 hv = __float2bfloat16(o);
            g_Oh[off + q] = hv;
            g_Ol[off + q] = __float2bfloat16(o - __bfloat162float(hv));
        }
    }
}

// ---------------------------------------------------------------------------
extern "C" void kernel_launch(void* const* d_in, const int* in_sizes, int n_in,
                              void* d_out, int out_size)
{
    const float* x    = (const float*)d_in[0];
    const float* Ae   = (const float*)d_in[1];
    const float* Ap   = (const float*)d_in[2];
    const float* Wqkv = (const float*)d_in[3];
    const float* bqkv = (const float*)d_in[4];
    const float* Wprj = (const float*)d_in[5];
    const float* bprj = (const float*)d_in[6];
    const float* Wg1  = (const float*)d_in[7];
    const float* bg1  = (const float*)d_in[8];
    const float* Wg2  = (const float*)d_in[9];
    const float* bg2  = (const float*)d_in[10];
    const float* Wb   = (const float*)d_in[11];
    const float* bb   = (const float*)d_in[12];
    const float* bsc  = (const float*)d_in[13];
    float* out = (float*)d_out;

    static bool init = false;
    static bf16 *xh, *xl, *wqh, *wql, *wph, *wpl;
    if (!init) {
        cudaFuncSetAttribute(k1_qkv_mma,  cudaFuncAttributeMaxDynamicSharedMemorySize, SM_GEMM_BYTES);
        cudaFuncSetAttribute(k4_proj_mma, cudaFuncAttributeMaxDynamicSharedMemorySize, SM_GEMM_BYTES);
        cudaFuncSetAttribute(kflash_mma,  cudaFuncAttributeMaxDynamicSharedMemorySize, KF_BYTES);
        cudaGetSymbolAddress((void**)&xh,  g_xh);
        cudaGetSymbolAddress((void**)&xl,  g_xl);
        cudaGetSymbolAddress((void**)&wqh, g_Wqh);
        cudaGetSymbolAddress((void**)&wql, g_Wql);
        cudaGetSymbolAddress((void**)&wph, g_Wph);
        cudaGetSymbolAddress((void**)&wpl, g_Wpl);
        init = true;
    }

    const int nx = B_*NN*D_;
    const int nq = 3*D_*D_;
    const int np = D_*D_;
    k0_conv<<<(nx+255)/256, 256>>>(x,    xh,  xl,  nx);
    k0_conv<<<(nq+255)/256, 256>>>(Wqkv, wqh, wql, nq);
    k0_conv<<<(np+255)/256, 256>>>(Wprj, wph, wpl, np);

    k1_qkv_mma <<<dim3(12, 64), 256, SM_GEMM_BYTES>>>(bqkv);
    k2_gate    <<<(B_*NN*NN)/256, 256>>>(Ae, Ap, Wg1, bg1, Wg2, bg2);
    kflash_mma <<<dim3(16, 64), 256, KF_BYTES>>>(Wb, bb, bsc);
    k4_proj_mma<<<dim3(4, 64), 256, SM_GEMM_BYTES>>>(bprj, out);
}

// round 7
// speedup vs baseline: 4.0561x; 1.0844x over previous
#include <cuda_runtime.h>
#include <cuda_bf16.h>
#include <mma.h>
#include <math.h>
#include <cstdint>

using namespace nvcuda;
typedef __nv_bfloat16 bf16;

#define B_   8
#define NN   1024
#define D_   512
#define H_   8
#define DH_  64
#define GH_  32
#define BH_  (B_*H_)
#define TAB  128            // gate-table grid resolution (129 nodes)

// Scratch (device globals)
__device__ float g_Ab[(size_t)B_*NN*NN];              // blended A [B,N,N]
__device__ float g_tab[129*129];                      // gate lookup table
__device__ bf16 g_qkvh[3u*BH_*NN*DH_];                // Q|K|V hi
__device__ bf16 g_qkvl[3u*BH_*NN*DH_];                // Q|K|V lo
__device__ bf16 g_xh[(size_t)B_*NN*D_];
__device__ bf16 g_xl[(size_t)B_*NN*D_];
__device__ bf16 g_Wqh[3*D_*D_];
__device__ bf16 g_Wql[3*D_*D_];
__device__ bf16 g_Wph[D_*D_];
__device__ bf16 g_Wpl[D_*D_];
__device__ bf16 g_Oh[(size_t)B_*NN*D_];
__device__ bf16 g_Ol[(size_t)B_*NN*D_];

// ---------------------------------------------------------------------------
__device__ __forceinline__ void cp16(void* smem_ptr, const void* gptr) {
    uint32_t s = (uint32_t)__cvta_generic_to_shared(smem_ptr);
    asm volatile("cp.async.cg.shared.global [%0], [%1], 16;" :: "r"(s), "l"(gptr));
}
#define CP_COMMIT() asm volatile("cp.async.commit_group;")
#define CP_WAIT(n)  asm volatile("cp.async.wait_group %0;" :: "n"(n))

__device__ __forceinline__ uint32_t pack_bf2(float a, float b) {
    __nv_bfloat162 t = __halves2bfloat162(__float2bfloat16(a), __float2bfloat16(b));
    return *reinterpret_cast<uint32_t*>(&t);
}

// ---------------------------------------------------------------------------
// K0: fp32 -> bf16 hi/lo split, three tensors in one launch
// ---------------------------------------------------------------------------
#define NX_ (B_*NN*D_)
#define NQ_ (3*D_*D_)
#define NP_ (D_*D_)
__global__ __launch_bounds__(256) void k0_conv3(
    const float* __restrict__ x, const float* __restrict__ wq,
    const float* __restrict__ wp)
{
    int idx = blockIdx.x * 256 + threadIdx.x;
    const float* src; bf16 *hi, *lo; int off;
    if (idx < NX_)             { src = x;  hi = g_xh;  lo = g_xl;  off = idx; }
    else if (idx < NX_ + NQ_)  { src = wq; hi = g_Wqh; lo = g_Wql; off = idx - NX_; }
    else if (idx < NX_+NQ_+NP_){ src = wp; hi = g_Wph; lo = g_Wpl; off = idx - NX_ - NQ_; }
    else return;
    float v = src[off];
    bf16 h = __float2bfloat16(v);
    hi[off] = h;
    lo[off] = __float2bfloat16(v - __bfloat162float(h));
}

// ---------------------------------------------------------------------------
// KTAB: build gate table g(a,p) at nodes (i/TAB, j/TAB), exact erf GELU
// ---------------------------------------------------------------------------
__global__ __launch_bounds__(256) void ktab_build(
    const float* __restrict__ Wg1, const float* __restrict__ bg1,
    const float* __restrict__ Wg2, const float* __restrict__ bg2)
{
    int idx = blockIdx.x * 256 + threadIdx.x;
    if (idx >= 129*129) return;
    const float a = (float)(idx % 129) / (float)TAB;
    const float p = (float)(idx / 129) / (float)TAB;
    float z = bg2[0];
    #pragma unroll 4
    for (int j = 0; j < GH_; j++) {
        float hpre = fmaf(Wg1[j*2], a, fmaf(Wg1[j*2+1], p, bg1[j]));
        float ge   = 0.5f * hpre * (1.0f + erff(hpre * 0.70710678118654752f));
        z = fmaf(Wg2[j], ge, z);
    }
    g_tab[idx] = 1.0f / (1.0f + expf(-z));
}

// ---------------------------------------------------------------------------
// K2: gate via bilinear table lookup -> A_blended
// ---------------------------------------------------------------------------
__global__ __launch_bounds__(256) void k2_gate_tab(
    const float* __restrict__ Ae, const float* __restrict__ Ap)
{
    const size_t idx = (size_t)blockIdx.x * 256 + threadIdx.x;
    const float a = Ae[idx];
    const float p = Ap[idx];
    float af = fminf(fmaxf(a, 0.0f), 0.999995f) * (float)TAB;
    float pf = fminf(fmaxf(p, 0.0f), 0.999995f) * (float)TAB;
    int ia = (int)af, ip = (int)pf;
    float fa = af - ia, fp = pf - ip;
    const float* t0 = g_tab + ip*129 + ia;
    float g00 = t0[0],   g01 = t0[1];
    float g10 = t0[129], g11 = t0[130];
    float g0 = fmaf(fa, g01 - g00, g00);
    float g1 = fmaf(fa, g11 - g10, g10);
    float g  = fmaf(fp, g1 - g0, g0);
    g_Ab[idx] = fmaf(g, a - p, p);
}

// ---------------------------------------------------------------------------
// WMMA 128x128 GEMM tile with cp.async double buffering (as R6, fixed stager)
// ---------------------------------------------------------------------------
#define ASLD 40
#define CSLD 136
#define STAGE_B 40960
#define SM_GEMM_BYTES (2*STAGE_B)

__device__ __forceinline__ void wmma_gemm_cp(
    const bf16* __restrict__ Ah, const bf16* __restrict__ Al,
    const bf16* __restrict__ Bh, const bf16* __restrict__ Bl,
    int lda, int ldb, int Ktot, int m0, int n0, char* sm)
{
    const int t   = threadIdx.x;
    const int wid = t >> 5;
    const int wm  = (wid >> 1) * 32;
    const int wn  = (wid & 1) * 64;

    wmma::fragment<wmma::accumulator, 16,16,16, float> acc[2][4];
    #pragma unroll
    for (int i = 0; i < 2; i++)
        #pragma unroll
        for (int j = 0; j < 4; j++) wmma::fill_fragment(acc[i][j], 0.0f);

    const int niter = Ktot / 32;
    auto issue = [&](int ch, int s) {
        const int kk = ch * 32;
        #pragma unroll
        for (int k = 0; k < 8; k++) {
            int c = k * 256 + t;
            int arr = c >> 9;
            int row = (c >> 2) & 127;
            int hh  = c & 3;
            const bf16* base = (arr == 0) ? Ah : (arr == 1) ? Al : (arr == 2) ? Bh : Bl;
            int roff = ((arr < 2) ? m0 : n0) + row;
            int ld   = (arr < 2) ? lda : ldb;
            cp16(sm + s*STAGE_B + arr*10240 + row*80 + hh*16,
                 base + (size_t)roff*ld + kk + hh*8);
        }
        CP_COMMIT();
    };

    issue(0, 0);
    for (int ch = 0; ch < niter; ch++) {
        const int s = ch & 1;
        if (ch + 1 < niter) { issue(ch + 1, s ^ 1); CP_WAIT(1); }
        else                { CP_WAIT(0); }
        __syncthreads();

        bf16* Ash = (bf16*)(sm + s*STAGE_B);
        bf16* Asl = Ash + 128*ASLD;
        bf16* Bsh = Asl + 128*ASLD;
        bf16* Bsl = Bsh + 128*ASLD;

        #pragma unroll
        for (int ks = 0; ks < 2; ks++) {
            const int ko = ks * 16;
            wmma::fragment<wmma::matrix_a, 16,16,16, bf16, wmma::row_major> ah[2], al[2];
            #pragma unroll
            for (int i = 0; i < 2; i++) {
                wmma::load_matrix_sync(ah[i], Ash + (wm + i*16)*ASLD + ko, ASLD);
                wmma::load_matrix_sync(al[i], Asl + (wm + i*16)*ASLD + ko, ASLD);
            }
            #pragma unroll
            for (int j = 0; j < 4; j++) {
                wmma::fragment<wmma::matrix_b, 16,16,16, bf16, wmma::col_major> bh, bl;
                wmma::load_matrix_sync(bh, Bsh + (wn + j*16)*ASLD + ko, ASLD);
                wmma::load_matrix_sync(bl, Bsl + (wn + j*16)*ASLD + ko, ASLD);
                #pragma unroll
                for (int i = 0; i < 2; i++) {
                    wmma::mma_sync(acc[i][j], ah[i], bh, acc[i][j]);
                    wmma::mma_sync(acc[i][j], ah[i], bl, acc[i][j]);
                    wmma::mma_sync(acc[i][j], al[i], bh, acc[i][j]);
                }
            }
        }
        __syncthreads();
    }

    float* Cs = (float*)sm;
    #pragma unroll
    for (int i = 0; i < 2; i++)
        #pragma unroll
        for (int j = 0; j < 4; j++)
            wmma::store_matrix_sync(Cs + (size_t)(wm + i*16)*CSLD + wn + j*16,
                                    acc[i][j], CSLD, wmma::mem_row_major);
    __syncthreads();
}

// ---------------------------------------------------------------------------
// K1: QKV = x @ W_qkv^T + b  -> scatter [3][B,H,N,DH] as bf16 hi/lo
// ---------------------------------------------------------------------------
__global__ __launch_bounds__(256, 2) void k1_qkv_mma(const float* __restrict__ bqkv)
{
    extern __shared__ char sm[];
    const int m0 = blockIdx.y * 128;
    const int n0 = blockIdx.x * 128;
    wmma_gemm_cp(g_xh, g_xl, g_Wqh, g_Wql, D_, D_, D_, m0, n0, sm);
    float* Cs = (float*)sm;

    const int t = threadIdx.x;
    for (int idx = t; idx < 128*128; idx += 256) {
        const int mi = idx >> 7, ni = idx & 127;
        const int m = m0 + mi, n = n0 + ni;
        const int b = m >> 10, iseq = m & 1023;
        const int cc = n >> 9, h = (n >> 6) & 7, d = n & 63;
        const float v = Cs[(size_t)mi*CSLD + ni] + bqkv[n];
        const size_t o = (((size_t)cc*B_ + b)*H_ + h)*NN*DH_ + (size_t)iseq*DH_ + d;
        bf16 hv = __float2bfloat16(v);
        g_qkvh[o] = hv;
        g_qkvl[o] = __float2bfloat16(v - __bfloat162float(hv));
    }
}

// ---------------------------------------------------------------------------
// K4: out = O @ W_proj^T + b_proj
// ---------------------------------------------------------------------------
__global__ __launch_bounds__(256, 2) void k4_proj_mma(
    const float* __restrict__ bp, float* __restrict__ out)
{
    extern __shared__ char sm[];
    const int m0 = blockIdx.y * 128;
    const int n0 = blockIdx.x * 128;
    wmma_gemm_cp(g_Oh, g_Ol, g_Wph, g_Wpl, D_, D_, D_, m0, n0, sm);
    float* Cs = (float*)sm;

    const int t = threadIdx.x;
    for (int idx = t; idx < 128*128; idx += 256) {
        const int mi = idx >> 7, ni = idx & 127;
        const int n = n0 + ni;
        out[(size_t)(m0 + mi) * D_ + n] = Cs[(size_t)mi*CSLD + ni] + bp[n];
    }
}

// ---------------------------------------------------------------------------
// KFLASH (WMMA): per block 64 q-rows of one (b,h). Clip => no-rescale softmax.
// ---------------------------------------------------------------------------
#define KF_QH 0
#define KF_QL 10240
#define KF_VH 20480
#define KF_VL 40960
#define KF_U  61440
#define KF_RS 102400
#define KF_BYTES 102656

__global__ __launch_bounds__(256, 2) void kflash_mma(
    const float* __restrict__ Wb, const float* __restrict__ bb,
    const float* __restrict__ bsc)
{
    extern __shared__ char sm[];
    const int t   = threadIdx.x;
    const int wid = t >> 5;
    const int mb  = blockIdx.x;
    const int bh  = blockIdx.y;
    const int b   = bh >> 3, h = bh & 7;
    const int m0  = mb * 64;

    const size_t Qoff = (size_t)bh * NN * DH_;
    const size_t Koff = ((size_t)BH_ + bh) * NN * DH_;
    const size_t Voff = ((size_t)2*BH_ + bh) * NN * DH_;
    const float* Abp  = g_Ab + (size_t)b * NN * NN;

    #pragma unroll
    for (int k = 0; k < 4; k++) {
        int c = k * 256 + t;
        int arr = c >> 9, row = (c >> 3) & 63, cc = c & 7;
        const bf16* src = (arr ? g_qkvl : g_qkvh) + Qoff + (size_t)(m0 + row)*DH_ + cc*8;
        cp16(sm + (arr ? KF_QL : KF_QH) + row*160 + cc*16, src);
    }
    CP_COMMIT();

    const int wmS = (wid >> 1) * 16, wnS = (wid & 1) * 64;
    const int wmO = (wid >> 1) * 16, wnO = (wid & 1) * 32;

    wmma::fragment<wmma::accumulator, 16,16,16, float> accO[2];
    #pragma unroll
    for (int j = 0; j < 2; j++) wmma::fill_fragment(accO[j], 0.0f);

    const int r_row = t >> 2;
    const int c0    = (t & 3) * 32;
    float rs = 0.0f;

    const float wbh = Wb[h], bbh = bb[h], sch = bsc[h];

    for (int tile = 0; tile < 8; tile++) {
        const int n0 = tile * 128;
        __syncthreads();

        #pragma unroll
        for (int k = 0; k < 16; k++) {
            int c = k * 256 + t;
            int arr = c >> 10, row = (c >> 3) & 127, cc = c & 7;
            const bf16* gb = (arr == 0) ? g_qkvh + Koff : (arr == 1) ? g_qkvl + Koff
                           : (arr == 2) ? g_qkvh + Voff : g_qkvl + Voff;
            char* db = (arr == 0) ? sm + KF_U : (arr == 1) ? sm + KF_U + 20480
                     : (arr == 2) ? sm + KF_VH : sm + KF_VL;
            cp16(db + row*160 + cc*16, gb + (size_t)(n0 + row)*DH_ + cc*8);
        }
        CP_COMMIT();
        CP_WAIT(0);
        __syncthreads();

        bf16* Qh = (bf16*)(sm + KF_QH);
        bf16* Ql = (bf16*)(sm + KF_QL);
        bf16* Kh = (bf16*)(sm + KF_U);
        bf16* Kl = (bf16*)(sm + KF_U + 20480);
        wmma::fragment<wmma::accumulator, 16,16,16, float> accS[4];
        #pragma unroll
        for (int j = 0; j < 4; j++) wmma::fill_fragment(accS[j], 0.0f);
        #pragma unroll
        for (int ks = 0; ks < 4; ks++) {
            const int ko = ks * 16;
            wmma::fragment<wmma::matrix_a, 16,16,16, bf16, wmma::row_major> ah, al;
            wmma::load_matrix_sync(ah, Qh + wmS*80 + ko, 80);
            wmma::load_matrix_sync(al, Ql + wmS*80 + ko, 80);
            #pragma unroll
            for (int j = 0; j < 4; j++) {
                wmma::fragment<wmma::matrix_b, 16,16,16, bf16, wmma::col_major> bh_f, bl_f;
                wmma::load_matrix_sync(bh_f, Kh + (wnS + j*16)*80 + ko, 80);
                wmma::load_matrix_sync(bl_f, Kl + (wnS + j*16)*80 + ko, 80);
                wmma::mma_sync(accS[j], ah, bh_f, accS[j]);
                wmma::mma_sync(accS[j], ah, bl_f, accS[j]);
                wmma::mma_sync(accS[j], al, bh_f, accS[j]);
            }
        }
        __syncthreads();
        float* Ssm = (float*)(sm + KF_U);
        #pragma unroll
        for (int j = 0; j < 4; j++)
            wmma::store_matrix_sync(Ssm + wmS*136 + wnS + j*16, accS[j], 136,
                                    wmma::mem_row_major);
        __syncthreads();

        // bias + softplus(__logf) + clip + exp ; rowsum
        float pv[32];
        {
            const float* srow = Ssm + r_row*136 + c0;
            const float* abr  = Abp + (size_t)(m0 + r_row)*NN + n0 + c0;
            #pragma unroll
            for (int q = 0; q < 8; q++) {
                float4 s4 = ((const float4*)srow)[q];
                float4 a4 = ((const float4*)abr)[q];
                float sv[4] = {s4.x, s4.y, s4.z, s4.w};
                float av[4] = {a4.x, a4.y, a4.z, a4.w};
                #pragma unroll
                for (int kq = 0; kq < 4; kq++) {
                    float z  = fmaf(av[kq], wbh, bbh);
                    float sp = fmaxf(z, 0.0f) + __logf(1.0f + __expf(-fabsf(z)));
                    float val = fmaf(sv[kq], 0.125f, sp * sch);
                    val = fminf(fmaxf(val, -50.0f), 50.0f);
                    float pq = __expf(val);
                    rs += pq;
                    pv[q*4 + kq] = pq;
                }
            }
        }
        __syncthreads();
        {
            uint4* Php = (uint4*)((bf16*)(sm + KF_U) + r_row*136 + c0);
            uint4* Plp = (uint4*)((bf16*)(sm + KF_U + 17408) + r_row*136 + c0);
            #pragma unroll
            for (int w4 = 0; w4 < 4; w4++) {
                uint32_t hw[4], lw[4];
                #pragma unroll
                for (int q = 0; q < 4; q++) {
                    float v0 = pv[w4*8 + q*2], v1 = pv[w4*8 + q*2 + 1];
                    bf16 h0 = __float2bfloat16(v0), h1 = __float2bfloat16(v1);
                    hw[q] = pack_bf2(v0, v1);
                    lw[q] = pack_bf2(v0 - __bfloat162float(h0),
                                     v1 - __bfloat162float(h1));
                }
                Php[w4] = make_uint4(hw[0], hw[1], hw[2], hw[3]);
                Plp[w4] = make_uint4(lw[0], lw[1], lw[2], lw[3]);
            }
        }
        __syncthreads();

        bf16* Ph = (bf16*)(sm + KF_U);
        bf16* Pl = (bf16*)(sm + KF_U + 17408);
        bf16* Vh = (bf16*)(sm + KF_VH);
        bf16* Vl = (bf16*)(sm + KF_VL);
        #pragma unroll
        for (int ks = 0; ks < 8; ks++) {
            const int ko = ks * 16;
            wmma::fragment<wmma::matrix_a, 16,16,16, bf16, wmma::row_major> pah, pal;
            wmma::load_matrix_sync(pah, Ph + wmO*136 + ko, 136);
            wmma::load_matrix_sync(pal, Pl + wmO*136 + ko, 136);
            #pragma unroll
            for (int j = 0; j < 2; j++) {
                wmma::fragment<wmma::matrix_b, 16,16,16, bf16, wmma::row_major> vbh, vbl;
                wmma::load_matrix_sync(vbh, Vh + ko*80 + wnO + j*16, 80);
                wmma::load_matrix_sync(vbl, Vl + ko*80 + wnO + j*16, 80);
                wmma::mma_sync(accO[j], pah, vbh, accO[j]);
                wmma::mma_sync(accO[j], pah, vbl, accO[j]);
                wmma::mma_sync(accO[j], pal, vbh, accO[j]);
            }
        }
    }

    __syncthreads();
    float* Osm = (float*)(sm + KF_U);
    #pragma unroll
    for (int j = 0; j < 2; j++)
        wmma::store_matrix_sync(Osm + wmO*72 + wnO + j*16, accO[j], 72,
                                wmma::mem_row_major);
    rs += __shfl_xor_sync(0xffffffffu, rs, 1, 4);
    rs += __shfl_xor_sync(0xffffffffu, rs, 2, 4);
    float* rowsum = (float*)(sm + KF_RS);
    if ((t & 3) == 0) rowsum[r_row] = rs;
    __syncthreads();

    {
        const int r  = t >> 2;
        const int cc = (t & 3) * 16;
        const float inv = 1.0f / rowsum[r];
        const size_t off = ((size_t)b*NN + m0 + r) * D_ + h*DH_ + cc;
        #pragma unroll
        for (int q = 0; q < 16; q++) {
            float o = Osm[r*72 + cc + q] * inv;
            bf16 hv = __float2bfloat16(o);
            g_Oh[off + q] = hv;
            g_Ol[off + q] = __float2bfloat16(o - __bfloat162float(hv));
        }
    }
}

// ---------------------------------------------------------------------------
extern "C" void kernel_launch(void* const* d_in, const int* in_sizes, int n_in,
                              void* d_out, int out_size)
{
    const float* x    = (const float*)d_in[0];
    const float* Ae   = (const float*)d_in[1];
    const float* Ap   = (const float*)d_in[2];
    const float* Wqkv = (const float*)d_in[3];
    const float* bqkv = (const float*)d_in[4];
    const float* Wprj = (const float*)d_in[5];
    const float* bprj = (const float*)d_in[6];
    const float* Wg1  = (const float*)d_in[7];
    const float* bg1  = (const float*)d_in[8];
    const float* Wg2  = (const float*)d_in[9];
    const float* bg2  = (const float*)d_in[10];
    const float* Wb   = (const float*)d_in[11];
    const float* bb   = (const float*)d_in[12];
    const float* bsc  = (const float*)d_in[13];
    float* out = (float*)d_out;

    static bool init = false;
    if (!init) {
        cudaFuncSetAttribute(k1_qkv_mma,  cudaFuncAttributeMaxDynamicSharedMemorySize, SM_GEMM_BYTES);
        cudaFuncSetAttribute(k4_proj_mma, cudaFuncAttributeMaxDynamicSharedMemorySize, SM_GEMM_BYTES);
        cudaFuncSetAttribute(kflash_mma,  cudaFuncAttributeMaxDynamicSharedMemorySize, KF_BYTES);
        init = true;
    }

    const int ntot = NX_ + NQ_ + NP_;
    k0_conv3  <<<(ntot+255)/256, 256>>>(x, Wqkv, Wprj);
    ktab_build<<<(129*129+255)/256, 256>>>(Wg1, bg1, Wg2, bg2);
    k1_qkv_mma <<<dim3(12, 64), 256, SM_GEMM_BYTES>>>(bqkv);
    k2_gate_tab<<<(B_*NN*NN)/256, 256>>>(Ae, Ap);
    kflash_mma <<<dim3(16, 64), 256, KF_BYTES>>>(Wb, bb, bsc);
    k4_proj_mma<<<dim3(4, 64), 256, SM_GEMM_BYTES>>>(bprj, out);
}